// round 5
// baseline (speedup 1.0000x reference)
#include <cuda_runtime.h>
#include <cstdint>

#define GS 96
#define CC 64               // 8*8 elements per block
#define B_DIM 64
#define THREADS 128
#define WARPS 4
#define TT 8                // tile: TT x TT (i,j) pairs per CTA
#define NT (GS / TT)        // 12 tiles per dimension

// out[b][i][j][c][k]: out[...][c][0] = x[b][i][c], out[...][c][1] = x[b][j][c]
// Per (b,i,j): 128 floats, pair-interleaved (xi[0],xj[0],xi[1],xj[1],...)
__global__ __launch_bounds__(THREADS) void gcom_kernel(const float* __restrict__ x,
                                                       float* __restrict__ out) {
    const int blk = blockIdx.x;              // 0 .. 64*144-1
    const int b   = blk / (NT * NT);
    const int rem = blk - b * (NT * NT);
    const int i0  = (rem / NT) * TT;
    const int j0  = (rem - (rem / NT) * NT) * TT;

    // Stage 8 i-rows + 8 j-rows (2 KB each)
    __shared__ float xi_s[TT * CC];
    __shared__ float xj_s[TT * CC];
    {
        const float4* si =
            reinterpret_cast<const float4*>(x + ((size_t)b * GS + i0) * CC);
        const float4* sj =
            reinterpret_cast<const float4*>(x + ((size_t)b * GS + j0) * CC);
        // TT*CC/4 = 128 float4 each; one pass per buffer with 128 threads
        reinterpret_cast<float4*>(xi_s)[threadIdx.x] = __ldg(si + threadIdx.x);
        reinterpret_cast<float4*>(xj_s)[threadIdx.x] = __ldg(sj + threadIdx.x);
    }
    __syncthreads();

    const int quad = threadIdx.x & 31;   // float4 index within a pair-row (32*16B = 512B)
    const int wid  = threadIdx.x >> 5;   // warp id 0..3 -> jj stride

    const float2* __restrict__ xi2 = reinterpret_cast<const float2*>(xi_s);
    const float2* __restrict__ xj2 = reinterpret_cast<const float2*>(xj_s);

    float4* __restrict__ ob =
        reinterpret_cast<float4*>(out) + (((size_t)b * GS + i0) * GS + j0) * 32;

    #pragma unroll
    for (int ii = 0; ii < TT; ii++) {
        const float2 xiv = xi2[ii * 32 + quad];
        float4* __restrict__ op = ob + (size_t)ii * GS * 32;
        #pragma unroll
        for (int jj = wid; jj < TT; jj += WARPS) {   // 2 iterations
            const float2 xjv = xj2[jj * 32 + quad];
            float4 v;
            v.x = xiv.x; v.y = xjv.x;
            v.z = xiv.y; v.w = xjv.y;
            __stcs(op + (size_t)jj * 32 + quad, v);  // streaming, evict-first
        }
    }
}

extern "C" void kernel_launch(void* const* d_in, const int* in_sizes, int n_in,
                              void* d_out, int out_size) {
    const float* x = (const float*)d_in[0];
    float* out = (float*)d_out;
    gcom_kernel<<<B_DIM * NT * NT, THREADS>>>(x, out);
}